// round 2
// baseline (speedup 1.0000x reference)
#include <cuda_runtime.h>

// ForwardKinematics: B=65536 batches, N=24 joints.
// d_in[0] = rotation_matrices (B,24,3,3) f32 ; d_in[1] = joints (B,24,3) f32
// d_out   = [ posed_joints (B,24,3) | rel_transforms (B,24,4,4) ] f32
//
// Strategy: block-staged streaming. 256 threads / 128 batches per block.
//  A: coalesced float4 global->smem loads (odd-strided smem, conflict-free)
//  B: 1 thread per batch walks the kinematic chain fully unrolled; parent
//     transforms held in a 6-deep register ring (max parent distance = 5);
//     global R overwrites local R in smem in place, t goes to a small region.
//  C: output-element-parallel coalesced float4 stores; rel last column
//     (t - R*j) and bottom row (0,0,0,1) synthesized on the fly.

#define THREADS 256
#define MB 128           // batches per block

static constexpr int NJ   = 24;
static constexpr int RSTR = 217;   // 216 + 1 (odd -> conflict-free per-batch access)
static constexpr int JSTR = 73;    // 72 + 1
static constexpr int TSTR = 73;
static constexpr int SMEM_FLOATS = MB * (RSTR + JSTR + TSTR);
static constexpr int SMEM_BYTES  = SMEM_FLOATS * 4;

__global__ __launch_bounds__(THREADS)
void fk_kernel(const float* __restrict__ rot,
               const float* __restrict__ jnt,
               float* __restrict__ out_pj,
               float* __restrict__ out_rel)
{
    extern __shared__ float sm[];
    float* sR = sm;                    // [MB][RSTR] local R -> global R (in place)
    float* sJ = sR + MB * RSTR;        // [MB][JSTR] absolute joints
    float* sT = sJ + MB * JSTR;        // [MB][TSTR] global translations

    const int tid = threadIdx.x;
    const long long blockBatch = (long long)blockIdx.x * MB;

    // ---------------- Phase A: coalesced loads into smem ----------------
    {
        const float4* rot4 = reinterpret_cast<const float4*>(rot + blockBatch * 216);
        #pragma unroll 4
        for (int idx = tid; idx < MB * 54; idx += THREADS) {
            float4 v = rot4[idx];
            int b = idx / 54, r = idx % 54;
            float* d = sR + b * RSTR + r * 4;
            d[0] = v.x; d[1] = v.y; d[2] = v.z; d[3] = v.w;
        }
        const float4* jnt4 = reinterpret_cast<const float4*>(jnt + blockBatch * 72);
        #pragma unroll 4
        for (int idx = tid; idx < MB * 18; idx += THREADS) {
            float4 v = jnt4[idx];
            int b = idx / 18, r = idx % 18;
            float* d = sJ + b * JSTR + r * 4;
            d[0] = v.x; d[1] = v.y; d[2] = v.z; d[3] = v.w;
        }
    }
    __syncthreads();

    // ---------------- Phase B: chain walk, 1 thread per batch ----------------
    if (tid < MB) {
        constexpr int PAR[NJ] = {-1,0,0,0,1,2,3,4,5,6,7,8,9,9,9,12,13,14,16,17,18,19,20,21};
        float rR[6][9];   // register ring of global rotations
        float rT[6][3];   // register ring of global translations
        float* mR = sR + tid * RSTR;
        float* mJ = sJ + tid * JSTR;
        float* mT = sT + tid * TSTR;

        #pragma unroll
        for (int i = 0; i < NJ; ++i) {
            float Rl[9];
            #pragma unroll
            for (int k = 0; k < 9; ++k) Rl[k] = mR[i * 9 + k];

            float Rg[9], Tg[3];
            if (i == 0) {
                #pragma unroll
                for (int k = 0; k < 9; ++k) Rg[k] = Rl[k];
                #pragma unroll
                for (int c = 0; c < 3; ++c) Tg[c] = mJ[c];
            } else {
                const int p  = PAR[i];
                const int ps = p % 6;
                float rel[3];
                #pragma unroll
                for (int c = 0; c < 3; ++c)
                    rel[c] = mJ[i * 3 + c] - mJ[p * 3 + c];
                #pragma unroll
                for (int r = 0; r < 3; ++r) {
                    const float a0 = rR[ps][r * 3 + 0];
                    const float a1 = rR[ps][r * 3 + 1];
                    const float a2 = rR[ps][r * 3 + 2];
                    #pragma unroll
                    for (int c = 0; c < 3; ++c)
                        Rg[r * 3 + c] = a0 * Rl[c] + a1 * Rl[3 + c] + a2 * Rl[6 + c];
                    Tg[r] = rT[ps][r] + a0 * rel[0] + a1 * rel[1] + a2 * rel[2];
                }
            }
            const int s = i % 6;
            #pragma unroll
            for (int k = 0; k < 9; ++k) { rR[s][k] = Rg[k]; mR[i * 9 + k] = Rg[k]; }
            #pragma unroll
            for (int c = 0; c < 3; ++c) { rT[s][c] = Tg[c]; mT[i * 3 + c] = Tg[c]; }
        }
    }
    __syncthreads();

    // ---------------- Phase C: coalesced output stores ----------------
    // posed_joints: (b, i, c) contiguous == sT layout (stride-free copy)
    {
        float4* pj4 = reinterpret_cast<float4*>(out_pj + blockBatch * 72);
        #pragma unroll 2
        for (int idx = tid; idx < MB * 18; idx += THREADS) {
            int b = idx / 18, r = idx % 18;
            const float* s = sT + b * TSTR + r * 4;
            pj4[idx] = make_float4(s[0], s[1], s[2], s[3]);
        }
    }
    // rel_transforms: each float4 = one row (i, r) of a batch's 4x4
    {
        float4* rel4 = reinterpret_cast<float4*>(out_rel + blockBatch * 384);
        #pragma unroll 2
        for (int idx = tid; idx < MB * 96; idx += THREADS) {
            int b = idx / 96, q = idx % 96;
            int i = q >> 2, r = q & 3;
            float4 v;
            if (r == 3) {
                v = make_float4(0.f, 0.f, 0.f, 1.f);
            } else {
                const float* Rrow = sR + b * RSTR + i * 9 + r * 3;
                const float* j    = sJ + b * JSTR + i * 3;
                const float  t    = sT[b * TSTR + i * 3 + r];
                v.x = Rrow[0]; v.y = Rrow[1]; v.z = Rrow[2];
                v.w = t - (Rrow[0] * j[0] + Rrow[1] * j[1] + Rrow[2] * j[2]);
            }
            rel4[idx] = v;
        }
    }
}

extern "C" void kernel_launch(void* const* d_in, const int* in_sizes, int n_in,
                              void* d_out, int out_size)
{
    const float* rot = (const float*)d_in[0];
    const float* jnt = (const float*)d_in[1];
    float* out = (float*)d_out;

    const long long B = 65536;
    float* out_pj  = out;
    float* out_rel = out + (size_t)B * NJ * 3;

    // Opt in to >48KB dynamic smem (idempotent; not a stream op, capture-safe).
    cudaFuncSetAttribute(fk_kernel, cudaFuncAttributeMaxDynamicSharedMemorySize, SMEM_BYTES);

    const int grid = (int)(B / MB);   // 512 blocks
    fk_kernel<<<grid, THREADS, SMEM_BYTES>>>(rot, jnt, out_pj, out_rel);
}

// round 5
// speedup vs baseline: 1.0291x; 1.0291x over previous
#include <cuda_runtime.h>

// ForwardKinematics: B=65536, N=24.
// R4: row-parallel chain walk (3 threads/batch) made race-free with one
//     __syncthreads per joint between local-R read and global-row write-back.
//     Phase B also computes rel w = t - Rg*j, so phase C is a pure copy.
//     smem 55.8KB -> 4 CTAs/SM.

#define THREADS 128
#define MB 32            // batches per block

static constexpr int NJ   = 24;
static constexpr int RSTR = 217;   // 216+1, odd -> conflict-free
static constexpr int JSTR = 73;    // 72+1
static constexpr int TSTR = 73;    // 72+1 (global translations t)
static constexpr int WSTR = 73;    // 72+1 (rel w = t - Rg*j)
static constexpr int SMEM_FLOATS = MB * (RSTR + JSTR + TSTR + WSTR);
static constexpr int SMEM_BYTES  = SMEM_FLOATS * 4;

__global__ __launch_bounds__(THREADS)
void fk_kernel(const float* __restrict__ rot,
               const float* __restrict__ jnt,
               float* __restrict__ out_pj,
               float* __restrict__ out_rel)
{
    extern __shared__ float sm[];
    float* sR = sm;                    // [MB][RSTR] local R -> global R (in place)
    float* sJ = sR + MB * RSTR;        // [MB][JSTR] absolute joints
    float* sT = sJ + MB * JSTR;        // [MB][TSTR] global t rows
    float* sW = sT + MB * TSTR;        // [MB][WSTR] rel fourth column

    const int tid = threadIdx.x;
    const long long blockBatch = (long long)blockIdx.x * MB;

    // ---------------- Phase A: coalesced loads into smem ----------------
    {
        const float4* rot4 = reinterpret_cast<const float4*>(rot + blockBatch * 216);
        #pragma unroll
        for (int it = 0; it < (MB * 54 + THREADS - 1) / THREADS; ++it) {
            int idx = tid + it * THREADS;
            if (idx < MB * 54) {
                float4 v = rot4[idx];
                int b = idx / 54, r = idx % 54;
                float* d = sR + b * RSTR + r * 4;
                d[0] = v.x; d[1] = v.y; d[2] = v.z; d[3] = v.w;
            }
        }
        const float4* jnt4 = reinterpret_cast<const float4*>(jnt + blockBatch * 72);
        #pragma unroll
        for (int it = 0; it < (MB * 18 + THREADS - 1) / THREADS; ++it) {
            int idx = tid + it * THREADS;
            if (idx < MB * 18) {
                float4 v = jnt4[idx];
                int b = idx / 18, r = idx % 18;
                float* d = sJ + b * JSTR + r * 4;
                d[0] = v.x; d[1] = v.y; d[2] = v.z; d[3] = v.w;
            }
        }
    }
    __syncthreads();

    // ------------ Phase B: row-parallel chain walk (3 threads/batch) ------------
    // Thread (b = tid&31, r = tid>>5) carries global row r of batch b.
    // Per joint: read local data -> compute -> __syncthreads -> write back.
    // The barrier makes the in-place overwrite of sR race-free across warps.
    {
        constexpr int PAR[NJ] = {-1,0,0,0,1,2,3,4,5,6,7,8,9,9,9,12,13,14,16,17,18,19,20,21};
        const bool active = (tid < 3 * MB);
        const int b = tid & (MB - 1);
        const int r = tid >> 5;         // 0..2 for active threads (warp-uniform)
        float ring[6][4];               // [slot][a0,a1,a2,t] global row r
        float* mR = sR + b * RSTR;
        float* mJ = sJ + b * JSTR;
        float* mT = sT + b * TSTR;
        float* mW = sW + b * WSTR;

        #pragma unroll
        for (int i = 0; i < NJ; ++i) {
            float row[4], w = 0.f;
            float j0 = 0.f, j1 = 0.f, j2 = 0.f;
            if (active) {
                j0 = mJ[i * 3 + 0]; j1 = mJ[i * 3 + 1]; j2 = mJ[i * 3 + 2];
                if (i == 0) {
                    row[0] = mR[r * 3 + 0];
                    row[1] = mR[r * 3 + 1];
                    row[2] = mR[r * 3 + 2];
                    row[3] = mJ[r];
                } else {
                    const int p  = PAR[i];
                    const int ps = p % 6;
                    const float a0 = ring[ps][0], a1 = ring[ps][1], a2 = ring[ps][2];
                    const float l00 = mR[i*9+0], l01 = mR[i*9+1], l02 = mR[i*9+2];
                    const float l10 = mR[i*9+3], l11 = mR[i*9+4], l12 = mR[i*9+5];
                    const float l20 = mR[i*9+6], l21 = mR[i*9+7], l22 = mR[i*9+8];
                    const float rel0 = j0 - mJ[p*3+0];
                    const float rel1 = j1 - mJ[p*3+1];
                    const float rel2 = j2 - mJ[p*3+2];
                    row[0] = a0 * l00 + a1 * l10 + a2 * l20;
                    row[1] = a0 * l01 + a1 * l11 + a2 * l21;
                    row[2] = a0 * l02 + a1 * l12 + a2 * l22;
                    row[3] = ring[ps][3] + a0 * rel0 + a1 * rel1 + a2 * rel2;
                }
                w = row[3] - (row[0] * j0 + row[1] * j1 + row[2] * j2);
            }
            __syncthreads();     // all local reads of joint i done before writes
            if (active) {
                const int s = i % 6;
                #pragma unroll
                for (int k = 0; k < 4; ++k) ring[s][k] = row[k];
                mR[i * 9 + r * 3 + 0] = row[0];   // global row overwrites local row
                mR[i * 9 + r * 3 + 1] = row[1];
                mR[i * 9 + r * 3 + 2] = row[2];
                mT[i * 3 + r]         = row[3];
                mW[i * 3 + r]         = w;
            }
        }
    }
    __syncthreads();

    // ---------------- Phase C: coalesced output stores (pure copy) ----------------
    // posed_joints: contiguous copy of sT
    {
        float4* pj4 = reinterpret_cast<float4*>(out_pj + blockBatch * 72);
        #pragma unroll
        for (int it = 0; it < (MB * 18 + THREADS - 1) / THREADS; ++it) {
            int idx = tid + it * THREADS;
            if (idx < MB * 18) {
                int b = idx / 18, r = idx % 18;
                const float* s = sT + b * TSTR + r * 4;
                pj4[idx] = make_float4(s[0], s[1], s[2], s[3]);
            }
        }
    }
    // rel_transforms: one float4 per (batch, joint, row)
    {
        float4* rel4 = reinterpret_cast<float4*>(out_rel + blockBatch * 384);
        #pragma unroll
        for (int it = 0; it < (MB * 96) / THREADS; ++it) {     // exactly 24 iters
            int idx = tid + it * THREADS;
            int b = idx / 96, q = idx % 96;
            int i = q >> 2, r = q & 3;
            float4 v;
            if (r == 3) {
                v = make_float4(0.f, 0.f, 0.f, 1.f);
            } else {
                const float* Rrow = sR + b * RSTR + i * 9 + r * 3;
                v.x = Rrow[0]; v.y = Rrow[1]; v.z = Rrow[2];
                v.w = sW[b * WSTR + i * 3 + r];
            }
            rel4[idx] = v;
        }
    }
}

extern "C" void kernel_launch(void* const* d_in, const int* in_sizes, int n_in,
                              void* d_out, int out_size)
{
    const float* rot = (const float*)d_in[0];
    const float* jnt = (const float*)d_in[1];
    float* out = (float*)d_out;

    const long long B = 65536;
    float* out_pj  = out;
    float* out_rel = out + (size_t)B * NJ * 3;

    cudaFuncSetAttribute(fk_kernel, cudaFuncAttributeMaxDynamicSharedMemorySize, SMEM_BYTES);

    const int grid = (int)(B / MB);   // 2048 blocks
    fk_kernel<<<grid, THREADS, SMEM_BYTES>>>(rot, jnt, out_pj, out_rel);
}

// round 6
// speedup vs baseline: 1.3096x; 1.2726x over previous
#include <cuda_runtime.h>

// ForwardKinematics: B=65536, N=24.
// R5: warp-autonomous design. Each warp owns 8 batches end-to-end:
//     A: coalesced float4 loads of its own gmem slice into private smem
//     B: row-parallel chain walk, lane=(b*4+r), r<3 active; the in-place
//        local->global R overwrite is guarded by one __syncwarp per joint
//     C: coalesced float4 stores of its own slice.
//     NO __syncthreads anywhere; warps never share data.

#define THREADS 128
#define MB 32            // batches per block (8 per warp)
#define BPW 8            // batches per warp

static constexpr int NJ   = 24;
static constexpr int RSTR = 217;   // 216+1, odd -> conflict-free
static constexpr int JSTR = 73;    // 72+1
static constexpr int TSTR = 73;    // global t rows
static constexpr int WSTR = 73;    // rel fourth column w = t - Rg*j
static constexpr int SMEM_FLOATS = MB * (RSTR + JSTR + TSTR + WSTR);
static constexpr int SMEM_BYTES  = SMEM_FLOATS * 4;

__global__ __launch_bounds__(THREADS)
void fk_kernel(const float* __restrict__ rot,
               const float* __restrict__ jnt,
               float* __restrict__ out_pj,
               float* __restrict__ out_rel)
{
    extern __shared__ float sm[];
    float* sR = sm;                    // [MB][RSTR] local R -> global R (in place)
    float* sJ = sR + MB * RSTR;        // [MB][JSTR] absolute joints
    float* sT = sJ + MB * JSTR;        // [MB][TSTR] global t
    float* sW = sT + MB * TSTR;        // [MB][WSTR] rel w

    const int tid  = threadIdx.x;
    const int warp = tid >> 5;
    const int lane = tid & 31;
    const int wb   = warp * BPW;                       // warp's first batch (block-local)
    const long long gBatch = (long long)blockIdx.x * MB + wb;   // warp's first batch (global)

    // ---------------- Phase A: per-warp coalesced loads ----------------
    {
        const float4* rot4 = reinterpret_cast<const float4*>(rot) + gBatch * 54;
        #pragma unroll
        for (int it = 0; it < 14; ++it) {              // 8*54 = 432 float4
            int idx = lane + it * 32;
            if (idx < BPW * 54) {
                float4 v = rot4[idx];
                int b = wb + idx / 54, r = idx % 54;
                float* d = sR + b * RSTR + r * 4;
                d[0] = v.x; d[1] = v.y; d[2] = v.z; d[3] = v.w;
            }
        }
        const float4* jnt4 = reinterpret_cast<const float4*>(jnt) + gBatch * 18;
        #pragma unroll
        for (int it = 0; it < 5; ++it) {               // 8*18 = 144 float4
            int idx = lane + it * 32;
            if (idx < BPW * 18) {
                float4 v = jnt4[idx];
                int b = wb + idx / 18, r = idx % 18;
                float* d = sJ + b * JSTR + r * 4;
                d[0] = v.x; d[1] = v.y; d[2] = v.z; d[3] = v.w;
            }
        }
    }
    __syncwarp();

    // ------- Phase B: row-parallel chain walk, all rows of a batch in-warp -------
    // lane = (b_local * 4 + r); r==3 lanes idle. One __syncwarp per joint orders
    // the read of joint i's local R before its in-place overwrite by global rows.
    {
        constexpr int PAR[NJ] = {-1,0,0,0,1,2,3,4,5,6,7,8,9,9,9,12,13,14,16,17,18,19,20,21};
        const int  b      = wb + (lane >> 2);
        const int  r      = lane & 3;
        const bool active = (r < 3);
        float ring[6][4];               // [slot][Rg_r0, Rg_r1, Rg_r2, t_r]
        float* mR = sR + b * RSTR;
        float* mJ = sJ + b * JSTR;
        float* mT = sT + b * TSTR;
        float* mW = sW + b * WSTR;

        #pragma unroll
        for (int i = 0; i < NJ; ++i) {
            float row[4] = {0.f, 0.f, 0.f, 0.f}, w = 0.f;
            if (active) {
                const float j0 = mJ[i * 3 + 0];
                const float j1 = mJ[i * 3 + 1];
                const float j2 = mJ[i * 3 + 2];
                if (i == 0) {
                    row[0] = mR[r * 3 + 0];
                    row[1] = mR[r * 3 + 1];
                    row[2] = mR[r * 3 + 2];
                    row[3] = mJ[r];
                } else {
                    const int p  = PAR[i];
                    const int ps = p % 6;
                    const float a0 = ring[ps][0], a1 = ring[ps][1], a2 = ring[ps][2];
                    const float l00 = mR[i*9+0], l01 = mR[i*9+1], l02 = mR[i*9+2];
                    const float l10 = mR[i*9+3], l11 = mR[i*9+4], l12 = mR[i*9+5];
                    const float l20 = mR[i*9+6], l21 = mR[i*9+7], l22 = mR[i*9+8];
                    const float rel0 = j0 - mJ[p*3+0];
                    const float rel1 = j1 - mJ[p*3+1];
                    const float rel2 = j2 - mJ[p*3+2];
                    row[0] = a0 * l00 + a1 * l10 + a2 * l20;
                    row[1] = a0 * l01 + a1 * l11 + a2 * l21;
                    row[2] = a0 * l02 + a1 * l12 + a2 * l22;
                    row[3] = ring[ps][3] + a0 * rel0 + a1 * rel1 + a2 * rel2;
                }
                w = row[3] - (row[0] * j0 + row[1] * j1 + row[2] * j2);
            }
            __syncwarp();        // reads of joint i done (warp-wide) before overwrite
            if (active) {
                const int s = i % 6;
                #pragma unroll
                for (int k = 0; k < 4; ++k) ring[s][k] = row[k];
                mR[i * 9 + r * 3 + 0] = row[0];
                mR[i * 9 + r * 3 + 1] = row[1];
                mR[i * 9 + r * 3 + 2] = row[2];
                mT[i * 3 + r]         = row[3];
                mW[i * 3 + r]         = w;
            }
        }
    }
    __syncwarp();

    // ---------------- Phase C: per-warp coalesced stores ----------------
    // posed_joints: contiguous copy of sT slice
    {
        float4* pj4 = reinterpret_cast<float4*>(out_pj) + gBatch * 18;
        #pragma unroll
        for (int it = 0; it < 5; ++it) {               // 8*18 = 144 float4
            int idx = lane + it * 32;
            if (idx < BPW * 18) {
                int b = wb + idx / 18, r = idx % 18;
                const float* s = sT + b * TSTR + r * 4;
                pj4[idx] = make_float4(s[0], s[1], s[2], s[3]);
            }
        }
    }
    // rel_transforms: one float4 per (batch, joint, row)
    {
        float4* rel4 = reinterpret_cast<float4*>(out_rel) + gBatch * 96;
        #pragma unroll
        for (int it = 0; it < 24; ++it) {              // 8*96 = 768 float4, exact
            int idx = lane + it * 32;
            int b = wb + idx / 96, q = idx % 96;
            int i = q >> 2, r = q & 3;
            float4 v;
            if (r == 3) {
                v = make_float4(0.f, 0.f, 0.f, 1.f);
            } else {
                const float* Rrow = sR + b * RSTR + i * 9 + r * 3;
                v.x = Rrow[0]; v.y = Rrow[1]; v.z = Rrow[2];
                v.w = sW[b * WSTR + i * 3 + r];
            }
            rel4[idx] = v;
        }
    }
}

extern "C" void kernel_launch(void* const* d_in, const int* in_sizes, int n_in,
                              void* d_out, int out_size)
{
    const float* rot = (const float*)d_in[0];
    const float* jnt = (const float*)d_in[1];
    float* out = (float*)d_out;

    const long long B = 65536;
    float* out_pj  = out;
    float* out_rel = out + (size_t)B * NJ * 3;

    cudaFuncSetAttribute(fk_kernel, cudaFuncAttributeMaxDynamicSharedMemorySize, SMEM_BYTES);

    const int grid = (int)(B / MB);   // 2048 blocks
    fk_kernel<<<grid, THREADS, SMEM_BYTES>>>(rot, jnt, out_pj, out_rel);
}

// round 7
// speedup vs baseline: 1.5300x; 1.1683x over previous
#include <cuda_runtime.h>

// ForwardKinematics: B=65536, N=24.
// R6: sync-free warp-autonomous chain walk with direct rel stores.
//  A: per-warp coalesced float4 loads (rot+joints) into smem (read-only after).
//  B: row-parallel chain walk, lane=(b*4+r); parent rows live in a register
//     ring -> sR is never written -> no hazards, no per-joint syncs.
//     Each lane's global row IS the rel row (Rg0,Rg1,Rg2, t-Rg*j): store it
//     straight to gmem as float4. r==3 lanes store (0,0,0,1).
//  C: tiny coalesced posed-joints copy from sT.

#define THREADS 128
#define MB 32            // batches per block (8 per warp)
#define BPW 8            // batches per warp

static constexpr int NJ   = 24;
static constexpr int RSTR = 217;   // 216+1, odd -> conflict-free
static constexpr int JSTR = 73;    // 72+1
static constexpr int TSTR = 73;    // global t rows (for posed_joints)
static constexpr int SMEM_FLOATS = MB * (RSTR + JSTR + TSTR);
static constexpr int SMEM_BYTES  = SMEM_FLOATS * 4;

__global__ __launch_bounds__(THREADS)
void fk_kernel(const float* __restrict__ rot,
               const float* __restrict__ jnt,
               float* __restrict__ out_pj,
               float* __restrict__ out_rel)
{
    extern __shared__ float sm[];
    float* sR = sm;                    // [MB][RSTR] local R (read-only after A)
    float* sJ = sR + MB * RSTR;        // [MB][JSTR] absolute joints
    float* sT = sJ + MB * JSTR;        // [MB][TSTR] global t

    const int tid  = threadIdx.x;
    const int warp = tid >> 5;
    const int lane = tid & 31;
    const int wb   = warp * BPW;
    const long long gBatch = (long long)blockIdx.x * MB + wb;

    // ---------------- Phase A: per-warp coalesced loads ----------------
    {
        const float4* rot4 = reinterpret_cast<const float4*>(rot) + gBatch * 54;
        #pragma unroll
        for (int it = 0; it < 14; ++it) {              // 8*54 = 432 float4
            int idx = lane + it * 32;
            if (idx < BPW * 54) {
                float4 v = rot4[idx];
                int b = wb + idx / 54, r = idx % 54;
                float* d = sR + b * RSTR + r * 4;
                d[0] = v.x; d[1] = v.y; d[2] = v.z; d[3] = v.w;
            }
        }
        const float4* jnt4 = reinterpret_cast<const float4*>(jnt) + gBatch * 18;
        #pragma unroll
        for (int it = 0; it < 5; ++it) {               // 8*18 = 144 float4
            int idx = lane + it * 32;
            if (idx < BPW * 18) {
                float4 v = jnt4[idx];
                int b = wb + idx / 18, r = idx % 18;
                float* d = sJ + b * JSTR + r * 4;
                d[0] = v.x; d[1] = v.y; d[2] = v.z; d[3] = v.w;
            }
        }
    }
    __syncwarp();

    // ------- Phase B: sync-free chain walk + direct rel stores -------
    {
        constexpr int PAR[NJ] = {-1,0,0,0,1,2,3,4,5,6,7,8,9,9,9,12,13,14,16,17,18,19,20,21};
        const int  bl     = lane >> 2;          // 0..7 local batch
        const int  b      = wb + bl;
        const int  r      = lane & 3;
        const bool active = (r < 3);
        float ring[6][4];                       // [slot][Rg_r0,Rg_r1,Rg_r2,t_r]
        const float* mR = sR + b * RSTR;
        const float* mJ = sJ + b * JSTR;
        float*       mT = sT + b * TSTR;
        float4* relW = reinterpret_cast<float4*>(out_rel) + gBatch * 96 + bl * 96;

        #pragma unroll
        for (int i = 0; i < NJ; ++i) {
            float4 v;
            if (active) {
                float row[4];
                const float j0 = mJ[i * 3 + 0];
                const float j1 = mJ[i * 3 + 1];
                const float j2 = mJ[i * 3 + 2];
                if (i == 0) {
                    row[0] = mR[r * 3 + 0];
                    row[1] = mR[r * 3 + 1];
                    row[2] = mR[r * 3 + 2];
                    row[3] = mJ[r];
                } else {
                    const int p  = PAR[i];
                    const int ps = p % 6;
                    const float a0 = ring[ps][0], a1 = ring[ps][1], a2 = ring[ps][2];
                    const float l00 = mR[i*9+0], l01 = mR[i*9+1], l02 = mR[i*9+2];
                    const float l10 = mR[i*9+3], l11 = mR[i*9+4], l12 = mR[i*9+5];
                    const float l20 = mR[i*9+6], l21 = mR[i*9+7], l22 = mR[i*9+8];
                    const float rel0 = j0 - mJ[p*3+0];
                    const float rel1 = j1 - mJ[p*3+1];
                    const float rel2 = j2 - mJ[p*3+2];
                    row[0] = a0 * l00 + a1 * l10 + a2 * l20;
                    row[1] = a0 * l01 + a1 * l11 + a2 * l21;
                    row[2] = a0 * l02 + a1 * l12 + a2 * l22;
                    row[3] = ring[ps][3] + a0 * rel0 + a1 * rel1 + a2 * rel2;
                }
                const int s = i % 6;
                #pragma unroll
                for (int k = 0; k < 4; ++k) ring[s][k] = row[k];
                mT[i * 3 + r] = row[3];                       // for posed_joints
                v = make_float4(row[0], row[1], row[2],
                                row[3] - (row[0]*j0 + row[1]*j1 + row[2]*j2));
            } else {
                v = make_float4(0.f, 0.f, 0.f, 1.f);          // bottom row
            }
            relW[i * 4 + r] = v;                              // direct rel store
        }
    }
    __syncwarp();

    // ---------------- Phase C: coalesced posed-joints copy ----------------
    {
        float4* pj4 = reinterpret_cast<float4*>(out_pj) + gBatch * 18;
        #pragma unroll
        for (int it = 0; it < 5; ++it) {               // 8*18 = 144 float4
            int idx = lane + it * 32;
            if (idx < BPW * 18) {
                int b = wb + idx / 18, r = idx % 18;
                const float* s = sT + b * TSTR + r * 4;
                pj4[idx] = make_float4(s[0], s[1], s[2], s[3]);
            }
        }
    }
}

extern "C" void kernel_launch(void* const* d_in, const int* in_sizes, int n_in,
                              void* d_out, int out_size)
{
    const float* rot = (const float*)d_in[0];
    const float* jnt = (const float*)d_in[1];
    float* out = (float*)d_out;

    const long long B = 65536;
    float* out_pj  = out;
    float* out_rel = out + (size_t)B * NJ * 3;

    cudaFuncSetAttribute(fk_kernel, cudaFuncAttributeMaxDynamicSharedMemorySize, SMEM_BYTES);

    const int grid = (int)(B / MB);   // 2048 blocks
    fk_kernel<<<grid, THREADS, SMEM_BYTES>>>(rot, jnt, out_pj, out_rel);
}